// round 1
// baseline (speedup 1.0000x reference)
#include <cuda_runtime.h>
#include <math.h>

#define NB 4
#define NN 4096
#define NM 4096
#define ND 256
#define ND0 128
#define NK 64
#define INV_TEMP 20.0f
#define THRESH 0.01f
#define EPS_G 1e-6f

// ---------------- scratch (device globals; no runtime allocation) ----------------
static __device__ float g_dA[NB * NN * ND];                    // 16 MB normalized A
static __device__ float g_dB[NB * NM * ND];                    // 16 MB normalized B
static __device__ float g_sim[(size_t)NB * NN * NM];           // 268 MB similarity
static __device__ unsigned g_rowmax[NB * NN];                  // encoded fp32 max
static __device__ unsigned g_colmax[NB * NM];
static __device__ float g_rowsum[NB * NN];
static __device__ float g_colsum[NB * NM];
static __device__ float g_rowsum_part[NB * NN * 32];           // deterministic partials
static __device__ float g_colsum_part[NB * NM * 32];
static __device__ unsigned long long g_rowpack[NB * NN];       // (P bits << 32) | (0x7FFFFFFF - m)
static __device__ unsigned g_colmaxP[NB * NM];                 // P >= 0 -> raw bits monotone

// monotone float<->uint encoding (handles negatives) for atomicMax
__device__ __forceinline__ unsigned encf(float f) {
    unsigned u = __float_as_uint(f);
    return (u & 0x80000000u) ? ~u : (u | 0x80000000u);
}
__device__ __forceinline__ float decf(unsigned u) {
    unsigned i = (u & 0x80000000u) ? (u & 0x7FFFFFFFu) : ~u;
    return __uint_as_float(i);
}

// ---------------- init ----------------
__global__ void init_kernel() {
    int i = blockIdx.x * blockDim.x + threadIdx.x;
    if (i < NB * NN) {
        g_rowmax[i] = 0u;
        g_colmax[i] = 0u;
        g_rowpack[i] = 0ull;
        g_colmaxP[i] = 0u;
    }
}

// ---------------- normalize descriptors ----------------
__global__ void normalize_kernel(const float* __restrict__ descA,
                                 const float* __restrict__ descB) {
    int row = blockIdx.x;  // 0 .. 2*NB*NN-1
    const float* src;
    float* dst;
    if (row < NB * NN) {
        src = descA + (size_t)row * ND;
        dst = g_dA + (size_t)row * ND;
    } else {
        int r = row - NB * NN;
        src = descB + (size_t)r * ND;
        dst = g_dB + (size_t)r * ND;
    }
    int t = threadIdx.x;  // 256
    float v = src[t];
    float s = v * v;
#pragma unroll
    for (int o = 16; o; o >>= 1) s += __shfl_xor_sync(0xffffffffu, s, o);
    __shared__ float ws[8];
    if ((t & 31) == 0) ws[t >> 5] = s;
    __syncthreads();
    float tot = ws[0] + ws[1] + ws[2] + ws[3] + ws[4] + ws[5] + ws[6] + ws[7];
    dst[t] = v / sqrtf(tot);
}

// ---------------- fp32 GEMM: sim = 20 * dA dB^T, fused row/col max ----------------
__global__ __launch_bounds__(256) void gemm_kernel() {
    int b = blockIdx.z;
    int m0 = blockIdx.x * 128;
    int n0 = blockIdx.y * 128;
    const float* A = g_dA + (size_t)b * NN * ND;
    const float* Bm = g_dB + (size_t)b * NM * ND;
    float* S = g_sim + (size_t)b * NN * NM;

    __shared__ float As[16][132];
    __shared__ float Bs[16][132];
    __shared__ unsigned scm[128];

    int tid = threadIdx.x;
    int tx = tid & 15;
    int ty = tid >> 4;

    float acc[8][8];
#pragma unroll
    for (int i = 0; i < 8; i++)
#pragma unroll
        for (int j = 0; j < 8; j++) acc[i][j] = 0.f;

    for (int k0 = 0; k0 < ND; k0 += 16) {
#pragma unroll
        for (int l = 0; l < 2; l++) {
            int idx = tid + l * 256;  // 0..511
            int r = idx >> 2;         // 0..127
            int f = (idx & 3) * 4;    // 0,4,8,12
            float4 va = *(const float4*)(A + (size_t)(n0 + r) * ND + k0 + f);
            As[f + 0][r] = va.x; As[f + 1][r] = va.y;
            As[f + 2][r] = va.z; As[f + 3][r] = va.w;
            float4 vb = *(const float4*)(Bm + (size_t)(m0 + r) * ND + k0 + f);
            Bs[f + 0][r] = vb.x; Bs[f + 1][r] = vb.y;
            Bs[f + 2][r] = vb.z; Bs[f + 3][r] = vb.w;
        }
        __syncthreads();
#pragma unroll
        for (int k = 0; k < 16; k++) {
            float a[8], bb[8];
            *(float4*)(a) = *(const float4*)&As[k][ty * 8];
            *(float4*)(a + 4) = *(const float4*)&As[k][ty * 8 + 4];
            *(float4*)(bb) = *(const float4*)&Bs[k][tx * 8];
            *(float4*)(bb + 4) = *(const float4*)&Bs[k][tx * 8 + 4];
#pragma unroll
            for (int i = 0; i < 8; i++)
#pragma unroll
                for (int j = 0; j < 8; j++) acc[i][j] = fmaf(a[i], bb[j], acc[i][j]);
        }
        __syncthreads();
    }

    // epilogue: scale, store, row/col maxima
    const float NEG_INF = __int_as_float(0xff800000);
    float cmax[8];
#pragma unroll
    for (int j = 0; j < 8; j++) cmax[j] = NEG_INF;

#pragma unroll
    for (int i = 0; i < 8; i++) {
        int row = n0 + ty * 8 + i;
        float vv[8];
        float rmax = NEG_INF;
#pragma unroll
        for (int j = 0; j < 8; j++) {
            float v = acc[i][j] * INV_TEMP;
            vv[j] = v;
            rmax = fmaxf(rmax, v);
            cmax[j] = fmaxf(cmax[j], v);
        }
        float4 s0 = make_float4(vv[0], vv[1], vv[2], vv[3]);
        float4 s1 = make_float4(vv[4], vv[5], vv[6], vv[7]);
        *(float4*)(S + (size_t)row * NM + m0 + tx * 8) = s0;
        *(float4*)(S + (size_t)row * NM + m0 + tx * 8 + 4) = s1;
#pragma unroll
        for (int o = 8; o; o >>= 1) rmax = fmaxf(rmax, __shfl_xor_sync(0xffffffffu, rmax, o));
        if (tx == 0) atomicMax(&g_rowmax[b * NN + row], encf(rmax));
    }

    if (tid < 128) scm[tid] = 0u;
    __syncthreads();
#pragma unroll
    for (int j = 0; j < 8; j++) atomicMax(&scm[tx * 8 + j], encf(cmax[j]));
    __syncthreads();
    if (tid < 128) atomicMax(&g_colmax[b * NM + m0 + tid], scm[tid]);
}

// ---------------- exp sums (deterministic partials) ----------------
__global__ __launch_bounds__(256) void sums_kernel() {
    int b = blockIdx.z;
    int m0 = blockIdx.x * 128;
    int n0 = blockIdx.y * 128;
    const float* S = g_sim + (size_t)b * NN * NM;
    int w = threadIdx.x >> 5;
    int lane = threadIdx.x & 31;
    int c = m0 + lane * 4;

    float cm[4], csum[4] = {0.f, 0.f, 0.f, 0.f};
#pragma unroll
    for (int q = 0; q < 4; q++) cm[q] = decf(g_colmax[b * NM + c + q]);

#pragma unroll 1
    for (int r = 0; r < 16; r++) {
        int row = n0 + w * 16 + r;
        float rm = decf(g_rowmax[b * NN + row]);
        float4 v = *(const float4*)(S + (size_t)row * NM + c);
        float rowpart = expf(v.x - rm) + expf(v.y - rm) + expf(v.z - rm) + expf(v.w - rm);
        csum[0] += expf(v.x - cm[0]);
        csum[1] += expf(v.y - cm[1]);
        csum[2] += expf(v.z - cm[2]);
        csum[3] += expf(v.w - cm[3]);
#pragma unroll
        for (int o = 16; o; o >>= 1) rowpart += __shfl_xor_sync(0xffffffffu, rowpart, o);
        if (lane == 0) g_rowsum_part[(b * NN + row) * 32 + blockIdx.x] = rowpart;
    }

    __shared__ float sc[8][128];
#pragma unroll
    for (int q = 0; q < 4; q++) sc[w][lane * 4 + q] = csum[q];
    __syncthreads();
    if (threadIdx.x < 128) {
        float s = 0.f;
#pragma unroll
        for (int ww = 0; ww < 8; ww++) s += sc[ww][threadIdx.x];
        g_colsum_part[(b * NM + m0 + threadIdx.x) * 32 + blockIdx.y] = s;
    }
}

__global__ void reduce_sums_kernel() {
    int i = blockIdx.x * blockDim.x + threadIdx.x;
    if (i < NB * NN) {
        float s = 0.f;
#pragma unroll
        for (int t = 0; t < 32; t++) s += g_rowsum_part[i * 32 + t];
        g_rowsum[i] = s;
    } else if (i < 2 * NB * NN) {
        int k = i - NB * NN;
        float s = 0.f;
#pragma unroll
        for (int t = 0; t < 32; t++) s += g_colsum_part[k * 32 + t];
        g_colsum[k] = s;
    }
}

// ---------------- P pass: row argmax of P, column max of P ----------------
__global__ __launch_bounds__(256) void pmat_kernel() {
    int b = blockIdx.z;
    int m0 = blockIdx.x * 128;
    int n0 = blockIdx.y * 128;
    const float* S = g_sim + (size_t)b * NN * NM;
    int w = threadIdx.x >> 5;
    int lane = threadIdx.x & 31;
    int c = m0 + lane * 4;

    float cm[4], cs[4], cpmax[4] = {0.f, 0.f, 0.f, 0.f};
#pragma unroll
    for (int q = 0; q < 4; q++) {
        cm[q] = decf(g_colmax[b * NM + c + q]);
        cs[q] = g_colsum[b * NM + c + q];
    }

#pragma unroll 1
    for (int r = 0; r < 16; r++) {
        int row = n0 + w * 16 + r;
        float rm = decf(g_rowmax[b * NN + row]);
        float rs = g_rowsum[b * NN + row];
        float4 v = *(const float4*)(S + (size_t)row * NM + c);
        float vals[4] = {v.x, v.y, v.z, v.w};
        float p[4];
#pragma unroll
        for (int q = 0; q < 4; q++) {
            p[q] = expf((vals[q] - rm) + (vals[q] - cm[q])) / (rs * cs[q]);
            cpmax[q] = fmaxf(cpmax[q], p[q]);
        }
        float best = p[0];
        int bm = c;
#pragma unroll
        for (int q = 1; q < 4; q++) {
            if (p[q] > best) { best = p[q]; bm = c + q; }
        }
#pragma unroll
        for (int o = 16; o; o >>= 1) {
            float ob = __shfl_xor_sync(0xffffffffu, best, o);
            int obm = __shfl_xor_sync(0xffffffffu, bm, o);
            if (ob > best || (ob == best && obm < bm)) { best = ob; bm = obm; }
        }
        if (lane == 0) {
            unsigned long long pk =
                ((unsigned long long)__float_as_uint(best) << 32) |
                (unsigned)(0x7FFFFFFF - bm);
            atomicMax(&g_rowpack[b * NN + row], pk);
        }
    }

    __shared__ unsigned scp[128];
    if (threadIdx.x < 128) scp[threadIdx.x] = 0u;
    __syncthreads();
#pragma unroll
    for (int q = 0; q < 4; q++) atomicMax(&scp[lane * 4 + q], __float_as_uint(cpmax[q]));
    __syncthreads();
    if (threadIdx.x < 128) atomicMax(&g_colmaxP[b * NM + m0 + threadIdx.x], scp[threadIdx.x]);
}

// ---------------- finalize: gather, weights, 2x2 solve, SVD gate, outputs ----------------
__global__ __launch_bounds__(64) void finalize_kernel(const float* __restrict__ kA,
                                                      const float* __restrict__ descA,
                                                      const float* __restrict__ kB,
                                                      const float* __restrict__ descB,
                                                      const float* __restrict__ W,
                                                      const float* __restrict__ bl,
                                                      float* __restrict__ out) {
    int gid = blockIdx.x;       // b*NN + n
    int b = gid >> 12;
    int t = threadIdx.x;        // 64 threads

    unsigned long long pk = g_rowpack[gid];
    int j = 0x7FFFFFFF - (int)(unsigned)(pk & 0xFFFFFFFFull);
    float Pij = __uint_as_float((unsigned)(pk >> 32));
    float cmj = __uint_as_float(g_colmaxP[b * NM + j]);
    bool valid = (Pij >= cmj) && (Pij > THRESH);

    __shared__ float sa[256], sb[256];
    const float* arow = descA + (size_t)gid * ND;
    const float* brow = descB + ((size_t)b * NM + j) * ND;
    *(float4*)(sa + t * 4) = *(const float4*)(arow + t * 4);
    *(float4*)(sb + t * 4) = *(const float4*)(brow + t * 4);
    __syncthreads();

    // thread t == k (0..63): weight w_k
    float xA = 0.f, xB = 0.f;
#pragma unroll 4
    for (int d = 0; d < ND0; d++) {
        float wd = W[d * NK + t];
        xA = fmaf(sa[d], wd, xA);
        xB = fmaf(sb[d], wd, xB);
    }
    xA += bl[t];
    xB += bl[t];
    // softplus = max(x,0) + log1p(exp(-|x|))
    float spA = fmaxf(xA, 0.f) + log1pf(expf(-fabsf(xA)));
    float spB = fmaxf(xB, 0.f) + log1pf(expf(-fabsf(xB)));
    float wk = sqrtf(spA * spB);

    float x0 = sa[ND0 + 2 * t], x1 = sa[ND0 + 2 * t + 1];
    float y0 = sb[ND0 + 2 * t], y1 = sb[ND0 + 2 * t + 1];

    float vals[7];
    vals[0] = wk * x0 * x0;   // g00
    vals[1] = wk * x0 * x1;   // g01
    vals[2] = wk * x1 * x1;   // g11
    vals[3] = wk * y0 * x0;   // c00
    vals[4] = wk * y0 * x1;   // c01
    vals[5] = wk * y1 * x0;   // c10
    vals[6] = wk * y1 * x1;   // c11

    __shared__ float red[2][7];
#pragma unroll
    for (int i = 0; i < 7; i++) {
        float v = vals[i];
#pragma unroll
        for (int o = 16; o; o >>= 1) v += __shfl_xor_sync(0xffffffffu, v, o);
        if ((t & 31) == 0) red[t >> 5][i] = v;
    }
    __syncthreads();

    if (t == 0) {
        float g00 = red[0][0] + red[1][0] + EPS_G;
        float g01 = red[0][1] + red[1][1];
        float g11 = red[0][2] + red[1][2] + EPS_G;
        float c00 = red[0][3] + red[1][3];
        float c01 = red[0][4] + red[1][4];
        float c10 = red[0][5] + red[1][5];
        float c11 = red[0][6] + red[1][6];

        float dg = g00 * g11 - g01 * g01;
        float e00 = (c00 * g11 - c01 * g01) / dg;
        float e01 = (c01 * g00 - c00 * g01) / dg;
        float e10 = (c10 * g11 - c11 * g01) / dg;
        float e11 = (c11 * g00 - c10 * g01) / dg;

        // M = est^T est
        float M00 = e00 * e00 + e10 * e10;
        float M01 = e00 * e01 + e10 * e11;
        float M11 = e01 * e01 + e11 * e11;
        float tr = M00 + M11;
        float dd = M00 * M11 - M01 * M01;
        float disc = sqrtf(fmaxf(0.25f * tr * tr - dd, 0.f));
        float lhi = 0.5f * tr + disc;
        float llo = fmaxf(0.5f * tr - disc, 0.f);
        float shi = sqrtf(lhi);
        float slo = sqrtf(llo);

        bool good = isfinite(shi + slo) && (shi < 3.0f) && (slo > (1.0f / 3.0f));
        float dete = e00 * e11 - e01 * e10;
        good = good && (dete > 0.f);
        bool vfinal = valid && good;

        // output packing: [matchesA (B*N*2)] [matchesB (B*N*2)] [j (B*N)] [valid (B*N)]
        const int BN = NB * NN;
        out[(size_t)gid * 2 + 0] = kA[(size_t)gid * 2 + 0];
        out[(size_t)gid * 2 + 1] = kA[(size_t)gid * 2 + 1];
        out[(size_t)BN * 2 + (size_t)gid * 2 + 0] = kB[((size_t)b * NM + j) * 2 + 0];
        out[(size_t)BN * 2 + (size_t)gid * 2 + 1] = kB[((size_t)b * NM + j) * 2 + 1];
        out[(size_t)BN * 4 + gid] = (float)j;
        out[(size_t)BN * 5 + gid] = vfinal ? 1.0f : 0.0f;
    }
}

// ---------------- launch ----------------
extern "C" void kernel_launch(void* const* d_in, const int* in_sizes, int n_in,
                              void* d_out, int out_size) {
    const float* kA = (const float*)d_in[0];
    const float* dA = (const float*)d_in[1];
    const float* kB = (const float*)d_in[2];
    const float* dB = (const float*)d_in[3];
    const float* W = (const float*)d_in[4];
    const float* bl = (const float*)d_in[5];
    float* out = (float*)d_out;

    init_kernel<<<(NB * NN + 255) / 256, 256>>>();
    normalize_kernel<<<2 * NB * NN, 256>>>(dA, dB);

    dim3 g(NM / 128, NN / 128, NB);
    gemm_kernel<<<g, 256>>>();
    sums_kernel<<<g, 256>>>();
    reduce_sums_kernel<<<(2 * NB * NN + 255) / 256, 256>>>();
    pmat_kernel<<<g, 256>>>();
    finalize_kernel<<<NB * NN, 64>>>(kA, dA, kB, dB, W, bl, out);
}

// round 3
// speedup vs baseline: 1.5899x; 1.5899x over previous
#include <cuda_runtime.h>
#include <cuda_fp16.h>
#include <cstdint>
#include <math.h>

#define NB 4
#define NN 4096
#define NM 4096
#define ND 256
#define ND0 128
#define NK 64
#define KP 768              // split-K': [hi|lo|hi] x [hi|hi|lo]
#define CHUNK 32
#define ITERS (KP / CHUNK)  // 24
#define THRESH 0.01f
#define EPS_G 1e-6f

// ---------------- scratch ----------------
static __device__ __align__(16) __half g_A16[(size_t)NB * NN * KP];   // 25 MB
static __device__ __align__(16) __half g_B16[(size_t)NB * NM * KP];   // 25 MB
static __device__ float g_sim[(size_t)NB * NN * NM];                  // 268 MB (holds e = exp(sim))
static __device__ float g_rowsum[NB * NN];
static __device__ float g_colsum[NB * NM];
static __device__ float g_rowsum_part[NB * NN * 32];
static __device__ float g_colsum_part[NB * NM * 32];
static __device__ unsigned long long g_rowpack[NB * NN];
static __device__ unsigned g_colmaxP[NB * NM];

__device__ __forceinline__ uint32_t smem_to_u32(const void* p) {
    uint32_t a;
    asm("{ .reg .u64 t; cvta.to.shared.u64 t, %1; cvt.u32.u64 %0, t; }" : "=r"(a) : "l"(p));
    return a;
}

// CUTLASS-style crosswise swizzle for 64B rows: 16B group XOR (row & 3)
__device__ __forceinline__ uint32_t swz(uint32_t r, uint32_t bytecol) {
    return r * 64 + ((((bytecol >> 4) & 3) ^ (r & 3)) << 4) + (bytecol & 15);
}

__device__ __forceinline__ void cpasync16(uint32_t dst, const void* src) {
    asm volatile("cp.async.cg.shared.global [%0], [%1], 16;" :: "r"(dst), "l"(src));
}

__device__ __forceinline__ void ldsm4(uint32_t& d0, uint32_t& d1, uint32_t& d2, uint32_t& d3,
                                      uint32_t addr) {
    asm volatile("ldmatrix.sync.aligned.m8n8.x4.shared.b16 {%0,%1,%2,%3}, [%4];"
                 : "=r"(d0), "=r"(d1), "=r"(d2), "=r"(d3) : "r"(addr));
}

__device__ __forceinline__ void mma16816(float* c, const uint32_t* a, const uint32_t* b) {
    asm volatile(
        "mma.sync.aligned.m16n8k16.row.col.f32.f16.f16.f32 "
        "{%0,%1,%2,%3}, {%4,%5,%6,%7}, {%8,%9}, {%0,%1,%2,%3};"
        : "+f"(c[0]), "+f"(c[1]), "+f"(c[2]), "+f"(c[3])
        : "r"(a[0]), "r"(a[1]), "r"(a[2]), "r"(a[3]), "r"(b[0]), "r"(b[1]));
}

// ---------------- init ----------------
__global__ void init_kernel() {
    int i = blockIdx.x * blockDim.x + threadIdx.x;
    if (i < NB * NN) {
        g_rowpack[i] = 0ull;
        g_colmaxP[i] = 0u;
    }
}

// ---------------- normalize + fp16 split ----------------
__global__ void normalize_split_kernel(const float* __restrict__ descA,
                                       const float* __restrict__ descB) {
    int row = blockIdx.x;  // 0 .. 2*NB*NN-1
    bool isA = row < NB * NN;
    const float* src = isA ? descA + (size_t)row * ND
                           : descB + (size_t)(row - NB * NN) * ND;
    __half* dst = isA ? g_A16 + (size_t)row * KP
                      : g_B16 + (size_t)(row - NB * NN) * KP;
    int t = threadIdx.x;  // 256
    float v = src[t];
    float s = v * v;
#pragma unroll
    for (int o = 16; o; o >>= 1) s += __shfl_xor_sync(0xffffffffu, s, o);
    __shared__ float ws[8];
    if ((t & 31) == 0) ws[t >> 5] = s;
    __syncthreads();
    float tot = ws[0] + ws[1] + ws[2] + ws[3] + ws[4] + ws[5] + ws[6] + ws[7];
    float nv = v / sqrtf(tot);
    __half hi = __float2half_rn(nv);
    __half lo = __float2half_rn(nv - __half2float(hi));
    // A' = [hi | lo | hi],  B' = [hi | hi | lo]
    dst[t] = hi;
    dst[256 + t] = isA ? lo : hi;
    dst[512 + t] = isA ? hi : lo;
}

// ---------------- HMMA fp16 GEMM, fused exp + partial row/col sums ----------------
// 128x128 tile per CTA, 8 warps (2 x 4), each warp 64x32 via m16n8k16.
__global__ __launch_bounds__(256) void gemm16_kernel() {
    __shared__ __align__(128) char As[2][8192];
    __shared__ __align__(128) char Bs[2][8192];
    __shared__ float rowred[128][4];
    __shared__ float colred[128][2];

    int tid = threadIdx.x, lane = tid & 31, wid = tid >> 5;
    int warp_m = wid & 1;   // 64-row block of problem-n rows (A rows)
    int warp_n = wid >> 1;  // 32-col block of problem-m cols (B rows)
    int b = blockIdx.z;
    int m0 = blockIdx.x * 128;  // B rows
    int n0 = blockIdx.y * 128;  // A rows
    const char* Ag = (const char*)(g_A16 + ((size_t)b * NN + n0) * KP);
    const char* Bg = (const char*)(g_B16 + ((size_t)b * NM + m0) * KP);

    uint32_t asb = smem_to_u32(As), bsb = smem_to_u32(Bs);

    int lr = tid >> 1;        // row 0..127 per load
    int ls = (tid & 1) * 2;   // seg 0 or 2 (two 16B segs each)

    // prefetch iter 0 into buf 0
    {
        const char* Ar = Ag + (size_t)lr * (KP * 2);
        const char* Br = Bg + (size_t)lr * (KP * 2);
#pragma unroll
        for (int s = 0; s < 2; s++) {
            uint32_t d = swz((uint32_t)lr, (uint32_t)(ls + s) * 16);
            cpasync16(asb + d, Ar + (ls + s) * 16);
            cpasync16(bsb + d, Br + (ls + s) * 16);
        }
        asm volatile("cp.async.commit_group;" ::: "memory");
    }

    float acc[4][4][4];
#pragma unroll
    for (int i = 0; i < 4; i++)
#pragma unroll
        for (int j = 0; j < 4; j++)
#pragma unroll
            for (int k = 0; k < 4; k++) acc[i][j][k] = 0.f;

#pragma unroll 1
    for (int it = 0; it < ITERS; ++it) {
        int buf = it & 1;
        if (it + 1 < ITERS) {
            const char* Ar = Ag + (size_t)lr * (KP * 2) + (it + 1) * 64;
            const char* Br = Bg + (size_t)lr * (KP * 2) + (it + 1) * 64;
            uint32_t ab = asb + (buf ^ 1) * 8192, bb = bsb + (buf ^ 1) * 8192;
#pragma unroll
            for (int s = 0; s < 2; s++) {
                uint32_t d = swz((uint32_t)lr, (uint32_t)(ls + s) * 16);
                cpasync16(ab + d, Ar + (ls + s) * 16);
                cpasync16(bb + d, Br + (ls + s) * 16);
            }
            asm volatile("cp.async.commit_group;" ::: "memory");
            asm volatile("cp.async.wait_group 1;" ::: "memory");
        } else {
            asm volatile("cp.async.wait_group 0;" ::: "memory");
        }
        __syncthreads();

        uint32_t ab = asb + buf * 8192, bb = bsb + buf * 8192;
#pragma unroll
        for (int ks = 0; ks < 2; ++ks) {
            uint32_t a[4][4];
#pragma unroll
            for (int mf = 0; mf < 4; ++mf) {
                uint32_t r = warp_m * 64 + mf * 16 + (lane & 15);
                uint32_t bc = ks * 32 + (lane >> 4) * 16;
                ldsm4(a[mf][0], a[mf][1], a[mf][2], a[mf][3], ab + swz(r, bc));
            }
            uint32_t bf[4][2];
#pragma unroll
            for (int np = 0; np < 2; ++np) {
                uint32_t r = warp_n * 32 + np * 16 + (lane & 7) + ((lane >> 4) << 3);
                uint32_t bc = ks * 32 + ((lane >> 3) & 1) * 16;
                uint32_t r0, r1, r2, r3;
                ldsm4(r0, r1, r2, r3, bb + swz(r, bc));
                bf[np * 2][0] = r0; bf[np * 2][1] = r1;
                bf[np * 2 + 1][0] = r2; bf[np * 2 + 1][1] = r3;
            }
#pragma unroll
            for (int mf = 0; mf < 4; ++mf)
#pragma unroll
                for (int nf = 0; nf < 4; ++nf) mma16816(acc[mf][nf], a[mf], bf[nf]);
        }
        __syncthreads();
    }

    // ---------- epilogue: e = exp(20*acc), store, partial row/col sums ----------
    int qt = lane >> 2;  // 0..7 row-in-8
    int qc = lane & 3;   // col pair
    float rsl[4][2];
    float csl[4][2];
#pragma unroll
    for (int i = 0; i < 4; i++) { rsl[i][0] = rsl[i][1] = 0.f; csl[i][0] = csl[i][1] = 0.f; }

    float* S = g_sim + (size_t)b * NN * NM;
#pragma unroll
    for (int mf = 0; mf < 4; ++mf) {
#pragma unroll
        for (int h = 0; h < 2; ++h) {
            int gr = n0 + warp_m * 64 + mf * 16 + qt + 8 * h;
            float* Sr = S + (size_t)gr * NM + m0 + warp_n * 32;
#pragma unroll
            for (int nf = 0; nf < 4; ++nf) {
                float e0 = expf(20.0f * acc[mf][nf][h * 2 + 0]);
                float e1 = expf(20.0f * acc[mf][nf][h * 2 + 1]);
                *(float2*)(Sr + nf * 8 + qc * 2) = make_float2(e0, e1);
                rsl[mf][h] += e0 + e1;
                csl[nf][0] += e0;
                csl[nf][1] += e1;
            }
        }
    }

    // row partials: reduce over the 4 lanes of a quad (same row)
#pragma unroll
    for (int mf = 0; mf < 4; ++mf)
#pragma unroll
        for (int h = 0; h < 2; ++h) {
            float v = rsl[mf][h];
            v += __shfl_xor_sync(0xffffffffu, v, 1);
            v += __shfl_xor_sync(0xffffffffu, v, 2);
            if (qc == 0) rowred[warp_m * 64 + mf * 16 + qt + 8 * h][warp_n] = v;
        }
    // col partials: reduce over qt (lanes with same col)
#pragma unroll
    for (int nf = 0; nf < 4; ++nf)
#pragma unroll
        for (int c = 0; c < 2; ++c) {
            float v = csl[nf][c];
            v += __shfl_xor_sync(0xffffffffu, v, 4);
            v += __shfl_xor_sync(0xffffffffu, v, 8);
            v += __shfl_xor_sync(0xffffffffu, v, 16);
            if (qt == 0) colred[warp_n * 32 + nf * 8 + qc * 2 + c][warp_m] = v;
        }
    __syncthreads();

    if (tid < 128) {
        float rv = rowred[tid][0] + rowred[tid][1] + rowred[tid][2] + rowred[tid][3];
        g_rowsum_part[((size_t)b * NN + n0 + tid) * 32 + blockIdx.x] = rv;
        float cv = colred[tid][0] + colred[tid][1];
        g_colsum_part[((size_t)b * NM + m0 + tid) * 32 + blockIdx.y] = cv;
    }
}

// ---------------- final sum reduction ----------------
__global__ void reduce_sums_kernel() {
    int i = blockIdx.x * blockDim.x + threadIdx.x;
    if (i < NB * NN) {
        float s = 0.f;
#pragma unroll
        for (int t = 0; t < 32; t++) s += g_rowsum_part[i * 32 + t];
        g_rowsum[i] = s;
    } else if (i < 2 * NB * NN) {
        int k = i - NB * NN;
        float s = 0.f;
#pragma unroll
        for (int t = 0; t < 32; t++) s += g_colsum_part[k * 32 + t];
        g_colsum[k] = s;
    }
}

// ---------------- P pass: row argmax of P, column max of P ----------------
// g_sim holds e = exp(sim); p = e^2 * rinv * cinv (uniform scales preserve compares)
__global__ __launch_bounds__(256) void pmat_kernel() {
    int b = blockIdx.z;
    int m0 = blockIdx.x * 128;
    int n0 = blockIdx.y * 128;
    const float* S = g_sim + (size_t)b * NN * NM;
    int w = threadIdx.x >> 5;
    int lane = threadIdx.x & 31;
    int c = m0 + lane * 4;

    float ci[4], cpmax[4] = {0.f, 0.f, 0.f, 0.f};
#pragma unroll
    for (int q = 0; q < 4; q++) ci[q] = 1.0f / g_colsum[b * NM + c + q];

#pragma unroll 1
    for (int r = 0; r < 16; r++) {
        int row = n0 + w * 16 + r;
        float ri = 1.0f / g_rowsum[b * NN + row];
        float4 v = *(const float4*)(S + (size_t)row * NM + c);
        float vals[4] = {v.x, v.y, v.z, v.w};
        float p[4];
#pragma unroll
        for (int q = 0; q < 4; q++) {
            p[q] = vals[q] * vals[q] * ri * ci[q];
            cpmax[q] = fmaxf(cpmax[q], p[q]);
        }
        float best = p[0];
        int bm = c;
#pragma unroll
        for (int q = 1; q < 4; q++) {
            if (p[q] > best) { best = p[q]; bm = c + q; }
        }
#pragma unroll
        for (int o = 16; o; o >>= 1) {
            float ob = __shfl_xor_sync(0xffffffffu, best, o);
            int obm = __shfl_xor_sync(0xffffffffu, bm, o);
            if (ob > best || (ob == best && obm < bm)) { best = ob; bm = obm; }
        }
        if (lane == 0) {
            unsigned long long pk =
                ((unsigned long long)__float_as_uint(best) << 32) |
                (unsigned)(0x7FFFFFFF - bm);
            atomicMax(&g_rowpack[b * NN + row], pk);
        }
    }

    __shared__ unsigned scp[128];
    if (threadIdx.x < 128) scp[threadIdx.x] = 0u;
    __syncthreads();
#pragma unroll
    for (int q = 0; q < 4; q++) atomicMax(&scp[lane * 4 + q], __float_as_uint(cpmax[q]));
    __syncthreads();
    if (threadIdx.x < 128) atomicMax(&g_colmaxP[b * NM + m0 + threadIdx.x], scp[threadIdx.x]);
}

// ---------------- finalize ----------------
__global__ __launch_bounds__(64) void finalize_kernel(const float* __restrict__ kA,
                                                      const float* __restrict__ descA,
                                                      const float* __restrict__ kB,
                                                      const float* __restrict__ descB,
                                                      const float* __restrict__ W,
                                                      const float* __restrict__ bl,
                                                      float* __restrict__ out) {
    int gid = blockIdx.x;  // b*NN + n
    int b = gid >> 12;
    int t = threadIdx.x;   // 64 threads

    unsigned long long pk = g_rowpack[gid];
    int j = 0x7FFFFFFF - (int)(unsigned)(pk & 0xFFFFFFFFull);
    float Pij = __uint_as_float((unsigned)(pk >> 32));
    float cmj = __uint_as_float(g_colmaxP[b * NM + j]);
    bool valid = (Pij >= cmj) && (Pij > THRESH);

    __shared__ float sa[256], sb_[256];
    const float* arow = descA + (size_t)gid * ND;
    const float* brow = descB + ((size_t)b * NM + j) * ND;
    *(float4*)(sa + t * 4) = *(const float4*)(arow + t * 4);
    *(float4*)(sb_ + t * 4) = *(const float4*)(brow + t * 4);
    __syncthreads();

    float xA = 0.f, xB = 0.f;
#pragma unroll 4
    for (int d = 0; d < ND0; d++) {
        float wd = W[d * NK + t];
        xA = fmaf(sa[d], wd, xA);
        xB = fmaf(sb_[d], wd, xB);
    }
    xA += bl[t];
    xB += bl[t];
    float spA = fmaxf(xA, 0.f) + log1pf(expf(-fabsf(xA)));
    float spB = fmaxf(xB, 0.f) + log1pf(expf(-fabsf(xB)));
    float wk = sqrtf(spA * spB);

    float x0 = sa[ND0 + 2 * t], x1 = sa[ND0 + 2 * t + 1];
    float y0 = sb_[ND0 + 2 * t], y1 = sb_[ND0 + 2 * t + 1];

    float vals[7];
    vals[0] = wk * x0 * x0;
    vals[1] = wk * x0 * x1;
    vals[2] = wk * x1 * x1;
    vals[3] = wk * y0 * x0;
    vals[4] = wk * y0 * x1;
    vals[5] = wk * y1 * x0;
    vals[6] = wk * y1 * x1;

    __shared__ float red[2][7];
#pragma unroll
    for (int i = 0; i < 7; i++) {
        float v = vals[i];
#pragma unroll
        for (int o = 16; o; o >>= 1) v += __shfl_xor_sync(0xffffffffu, v, o);
        if ((t & 31) == 0) red[t >> 5][i] = v;
    }
    __syncthreads();

    if (t == 0) {
        float g00 = red[0][0] + red[1][0] + EPS_G;
        float g01 = red[0][1] + red[1][1];
        float g11 = red[0][2] + red[1][2] + EPS_G;
        float c00 = red[0][3] + red[1][3];
        float c01 = red[0][4] + red[1][4];
        float c10 = red[0][5] + red[1][5];
        float c11 = red[0][6] + red[1][6];

        float dg = g00 * g11 - g01 * g01;
        float e00 = (c00 * g11 - c01 * g01) / dg;
        float e01 = (c01 * g00 - c00 * g01) / dg;
        float e10 = (c10 * g11 - c11 * g01) / dg;
        float e11 = (c11 * g00 - c10 * g01) / dg;

        float M00 = e00 * e00 + e10 * e10;
        float M01 = e00 * e01 + e10 * e11;
        float M11 = e01 * e01 + e11 * e11;
        float tr = M00 + M11;
        float dd = M00 * M11 - M01 * M01;
        float disc = sqrtf(fmaxf(0.25f * tr * tr - dd, 0.f));
        float shi = sqrtf(0.5f * tr + disc);
        float slo = sqrtf(fmaxf(0.5f * tr - disc, 0.f));

        bool good = isfinite(shi + slo) && (shi < 3.0f) && (slo > (1.0f / 3.0f));
        float dete = e00 * e11 - e01 * e10;
        good = good && (dete > 0.f);
        bool vfinal = valid && good;

        const int BN = NB * NN;
        out[(size_t)gid * 2 + 0] = kA[(size_t)gid * 2 + 0];
        out[(size_t)gid * 2 + 1] = kA[(size_t)gid * 2 + 1];
        out[(size_t)BN * 2 + (size_t)gid * 2 + 0] = kB[((size_t)b * NM + j) * 2 + 0];
        out[(size_t)BN * 2 + (size_t)gid * 2 + 1] = kB[((size_t)b * NM + j) * 2 + 1];
        out[(size_t)BN * 4 + gid] = (float)j;
        out[(size_t)BN * 5 + gid] = vfinal ? 1.0f : 0.0f;
    }
}

// ---------------- launch ----------------
extern "C" void kernel_launch(void* const* d_in, const int* in_sizes, int n_in,
                              void* d_out, int out_size) {
    const float* kA = (const float*)d_in[0];
    const float* dA = (const float*)d_in[1];
    const float* kB = (const float*)d_in[2];
    const float* dB = (const float*)d_in[3];
    const float* W = (const float*)d_in[4];
    const float* bl = (const float*)d_in[5];
    float* out = (float*)d_out;

    init_kernel<<<(NB * NN + 255) / 256, 256>>>();
    normalize_split_kernel<<<2 * NB * NN, 256>>>(dA, dB);

    dim3 g(NM / 128, NN / 128, NB);
    gemm16_kernel<<<g, 256>>>();
    reduce_sums_kernel<<<(2 * NB * NN + 255) / 256, 256>>>();
    pmat_kernel<<<g, 256>>>();
    finalize_kernel<<<NB * NN, 64>>>(kA, dA, kB, dB, W, bl, out);
}

// round 4
// speedup vs baseline: 1.6436x; 1.0338x over previous
#include <cuda_runtime.h>
#include <cuda_fp16.h>
#include <cstdint>
#include <math.h>

#define NB 4
#define NN 4096
#define NM 4096
#define ND 256
#define ND0 128
#define NK 64
#define KP 768              // split-K': [hi|lo|hi] x [hi|hi|lo]
#define ITERS 24            // KP / 32
#define THRESH 0.01f
#define EPS_G 1e-6f

// ---------------- scratch ----------------
static __device__ __align__(16) __half g_A16[(size_t)NB * NN * KP];   // 25 MB
static __device__ __align__(16) __half g_B16[(size_t)NB * NM * KP];   // 25 MB
static __device__ float g_sim[(size_t)NB * NN * NM];                  // 268 MB (holds e = exp(sim))
static __device__ float g_rowsum[NB * NN];
static __device__ float g_colsum[NB * NM];
static __device__ float g_rowsum_part[NB * NN * 32];
static __device__ float g_colsum_part[NB * NM * 32];
static __device__ unsigned long long g_rowpack[NB * NN];
static __device__ unsigned g_colmaxP[NB * NM];

__device__ __forceinline__ uint32_t smem_to_u32(const void* p) {
    uint32_t a;
    asm("{ .reg .u64 t; cvta.to.shared.u64 t, %1; cvt.u32.u64 %0, t; }" : "=r"(a) : "l"(p));
    return a;
}

// CUTLASS-style crosswise swizzle for 64B rows: 16B group XOR (row & 3)
__device__ __forceinline__ uint32_t swz(uint32_t r, uint32_t bytecol) {
    return r * 64 + ((((bytecol >> 4) & 3) ^ (r & 3)) << 4) + (bytecol & 15);
}

__device__ __forceinline__ void cpasync16(uint32_t dst, const void* src) {
    asm volatile("cp.async.cg.shared.global [%0], [%1], 16;" :: "r"(dst), "l"(src));
}

__device__ __forceinline__ void ldsm4(uint32_t& d0, uint32_t& d1, uint32_t& d2, uint32_t& d3,
                                      uint32_t addr) {
    asm volatile("ldmatrix.sync.aligned.m8n8.x4.shared.b16 {%0,%1,%2,%3}, [%4];"
                 : "=r"(d0), "=r"(d1), "=r"(d2), "=r"(d3) : "r"(addr));
}

__device__ __forceinline__ void mma16816(float* c, const uint32_t* a, const uint32_t* b) {
    asm volatile(
        "mma.sync.aligned.m16n8k16.row.col.f32.f16.f16.f32 "
        "{%0,%1,%2,%3}, {%4,%5,%6,%7}, {%8,%9}, {%0,%1,%2,%3};"
        : "+f"(c[0]), "+f"(c[1]), "+f"(c[2]), "+f"(c[3])
        : "r"(a[0]), "r"(a[1]), "r"(a[2]), "r"(a[3]), "r"(b[0]), "r"(b[1]));
}

// ---------------- normalize + fp16 split (init folded in) ----------------
__global__ void normalize_split_kernel(const float* __restrict__ descA,
                                       const float* __restrict__ descB) {
    int row = blockIdx.x;  // 0 .. 2*NB*NN-1
    bool isA = row < NB * NN;
    if (isA && threadIdx.x == 0) {
        g_rowpack[row] = 0ull;
        g_colmaxP[row] = 0u;
    }
    const float* src = isA ? descA + (size_t)row * ND
                           : descB + (size_t)(row - NB * NN) * ND;
    __half* dst = isA ? g_A16 + (size_t)row * KP
                      : g_B16 + (size_t)(row - NB * NN) * KP;
    int t = threadIdx.x;  // 256
    float v = src[t];
    float s = v * v;
#pragma unroll
    for (int o = 16; o; o >>= 1) s += __shfl_xor_sync(0xffffffffu, s, o);
    __shared__ float ws[8];
    if ((t & 31) == 0) ws[t >> 5] = s;
    __syncthreads();
    float tot = ws[0] + ws[1] + ws[2] + ws[3] + ws[4] + ws[5] + ws[6] + ws[7];
    float nv = v / sqrtf(tot);
    __half hi = __float2half_rn(nv);
    __half lo = __float2half_rn(nv - __half2float(hi));
    // A' = [hi | lo | hi],  B' = [hi | hi | lo]
    dst[t] = hi;
    dst[256 + t] = isA ? lo : hi;
    dst[512 + t] = isA ? hi : lo;
}

// ---------------- HMMA fp16 GEMM, 3-stage pipeline, fused exp + partial sums ----------------
// 128x128 tile per CTA, 8 warps (2 x 4), each warp 64x32 via m16n8k16.
__global__ __launch_bounds__(256, 2) void gemm16_kernel() {
    __shared__ __align__(128) char buf[49152];  // 3 stages x (A 8KB + B 8KB)

    int tid = threadIdx.x, lane = tid & 31, wid = tid >> 5;
    int warp_m = wid & 1;   // 64-row block of A rows
    int warp_n = wid >> 1;  // 32-row block of B rows
    int b = blockIdx.z;
    int m0 = blockIdx.x * 128;  // B rows
    int n0 = blockIdx.y * 128;  // A rows
    const char* Ag = (const char*)(g_A16 + ((size_t)b * NN + n0) * KP);
    const char* Bg = (const char*)(g_B16 + ((size_t)b * NM + m0) * KP);

    uint32_t sbase = smem_to_u32(buf);

    int lr = tid >> 1;        // row 0..127 per load
    int ls = (tid & 1) * 2;   // seg 0 or 2 (two 16B segs each)

    // prefetch stages 0, 1
#pragma unroll
    for (int it = 0; it < 2; ++it) {
        const char* Ar = Ag + (size_t)lr * (KP * 2) + it * 64;
        const char* Br = Bg + (size_t)lr * (KP * 2) + it * 64;
        uint32_t ab = sbase + it * 8192, bb = sbase + 24576 + it * 8192;
#pragma unroll
        for (int s = 0; s < 2; s++) {
            uint32_t d = swz((uint32_t)lr, (uint32_t)(ls + s) * 16);
            cpasync16(ab + d, Ar + (ls + s) * 16);
            cpasync16(bb + d, Br + (ls + s) * 16);
        }
        asm volatile("cp.async.commit_group;" ::: "memory");
    }

    float acc[4][4][4];
#pragma unroll
    for (int i = 0; i < 4; i++)
#pragma unroll
        for (int j = 0; j < 4; j++)
#pragma unroll
            for (int k = 0; k < 4; k++) acc[i][j][k] = 0.f;

#pragma unroll 1
    for (int it = 0; it < ITERS; ++it) {
        if (it < ITERS - 2) {
            asm volatile("cp.async.wait_group 1;" ::: "memory");
        } else {
            asm volatile("cp.async.wait_group 0;" ::: "memory");
        }
        __syncthreads();

        if (it + 2 < ITERS) {
            int it2 = it + 2, slot2 = it2 % 3;
            const char* Ar = Ag + (size_t)lr * (KP * 2) + it2 * 64;
            const char* Br = Bg + (size_t)lr * (KP * 2) + it2 * 64;
            uint32_t ab = sbase + slot2 * 8192, bb = sbase + 24576 + slot2 * 8192;
#pragma unroll
            for (int s = 0; s < 2; s++) {
                uint32_t d = swz((uint32_t)lr, (uint32_t)(ls + s) * 16);
                cpasync16(ab + d, Ar + (ls + s) * 16);
                cpasync16(bb + d, Br + (ls + s) * 16);
            }
            asm volatile("cp.async.commit_group;" ::: "memory");
        }

        int slot = it % 3;
        uint32_t ab = sbase + slot * 8192, bb = sbase + 24576 + slot * 8192;
#pragma unroll
        for (int ks = 0; ks < 2; ++ks) {
            uint32_t a[4][4];
#pragma unroll
            for (int mf = 0; mf < 4; ++mf) {
                uint32_t r = warp_m * 64 + mf * 16 + (lane & 15);
                uint32_t bc = ks * 32 + (lane >> 4) * 16;
                ldsm4(a[mf][0], a[mf][1], a[mf][2], a[mf][3], ab + swz(r, bc));
            }
            uint32_t bf[4][2];
#pragma unroll
            for (int np = 0; np < 2; ++np) {
                uint32_t r = warp_n * 32 + np * 16 + (lane & 7) + ((lane >> 4) << 3);
                uint32_t bc = ks * 32 + ((lane >> 3) & 1) * 16;
                uint32_t r0, r1, r2, r3;
                ldsm4(r0, r1, r2, r3, bb + swz(r, bc));
                bf[np * 2][0] = r0; bf[np * 2][1] = r1;
                bf[np * 2 + 1][0] = r2; bf[np * 2 + 1][1] = r3;
            }
#pragma unroll
            for (int mf = 0; mf < 4; ++mf)
#pragma unroll
                for (int nf = 0; nf < 4; ++nf) mma16816(acc[mf][nf], a[mf], bf[nf]);
        }
    }
    __syncthreads();  // all compute done; safe to reuse buf as reduction scratch

    float (*rowred)[4] = (float(*)[4])buf;            // 128*4 floats
    float (*colred)[2] = (float(*)[2])(buf + 2048);   // 128*2 floats

    // ---------- epilogue: e = exp(20*acc), streaming store, partial row/col sums ----------
    int qt = lane >> 2;  // 0..7 row-in-8
    int qc = lane & 3;   // col pair
    float rsl[4][2];
    float csl[4][2];
#pragma unroll
    for (int i = 0; i < 4; i++) { rsl[i][0] = rsl[i][1] = 0.f; csl[i][0] = csl[i][1] = 0.f; }

    float* S = g_sim + (size_t)b * NN * NM;
#pragma unroll
    for (int mf = 0; mf < 4; ++mf) {
#pragma unroll
        for (int h = 0; h < 2; ++h) {
            int gr = n0 + warp_m * 64 + mf * 16 + qt + 8 * h;
            float* Sr = S + (size_t)gr * NM + m0 + warp_n * 32;
#pragma unroll
            for (int nf = 0; nf < 4; ++nf) {
                float e0 = expf(20.0f * acc[mf][nf][h * 2 + 0]);
                float e1 = expf(20.0f * acc[mf][nf][h * 2 + 1]);
                __stcs((float2*)(Sr + nf * 8 + qc * 2), make_float2(e0, e1));
                rsl[mf][h] += e0 + e1;
                csl[nf][0] += e0;
                csl[nf][1] += e1;
            }
        }
    }

    // row partials: reduce over the 4 lanes of a quad (same row)
#pragma unroll
    for (int mf = 0; mf < 4; ++mf)
#pragma unroll
        for (int h = 0; h < 2; ++h) {
            float v = rsl[mf][h];
            v += __shfl_xor_sync(0xffffffffu, v, 1);
            v += __shfl_xor_sync(0xffffffffu, v, 2);
            if (qc == 0) rowred[warp_m * 64 + mf * 16 + qt + 8 * h][warp_n] = v;
        }
    // col partials: reduce over qt (lanes with same col)
#pragma unroll
    for (int nf = 0; nf < 4; ++nf)
#pragma unroll
        for (int c = 0; c < 2; ++c) {
            float v = csl[nf][c];
            v += __shfl_xor_sync(0xffffffffu, v, 4);
            v += __shfl_xor_sync(0xffffffffu, v, 8);
            v += __shfl_xor_sync(0xffffffffu, v, 16);
            if (qt == 0) colred[warp_n * 32 + nf * 8 + qc * 2 + c][warp_m] = v;
        }
    __syncthreads();

    if (tid < 128) {
        float rv = rowred[tid][0] + rowred[tid][1] + rowred[tid][2] + rowred[tid][3];
        g_rowsum_part[((size_t)b * NN + n0 + tid) * 32 + blockIdx.x] = rv;
        float cv = colred[tid][0] + colred[tid][1];
        g_colsum_part[((size_t)b * NM + m0 + tid) * 32 + blockIdx.y] = cv;
    }
}

// ---------------- final sum reduction: one warp per output ----------------
__global__ void reduce_sums_kernel() {
    int warp = (blockIdx.x * blockDim.x + threadIdx.x) >> 5;  // 0..32767
    int lane = threadIdx.x & 31;
    if (warp < NB * NN) {
        float v = g_rowsum_part[warp * 32 + lane];
#pragma unroll
        for (int o = 16; o; o >>= 1) v += __shfl_xor_sync(0xffffffffu, v, o);
        if (lane == 0) g_rowsum[warp] = v;
    } else {
        int k = warp - NB * NN;
        float v = g_colsum_part[k * 32 + lane];
#pragma unroll
        for (int o = 16; o; o >>= 1) v += __shfl_xor_sync(0xffffffffu, v, o);
        if (lane == 0) g_colsum[k] = v;
    }
}

// ---------------- P pass: row argmax of P, column max of P ----------------
// g_sim holds e = exp(sim); p = e^2 * rinv * cinv (uniform scales preserve compares)
__global__ __launch_bounds__(256) void pmat_kernel() {
    int b = blockIdx.z;
    int m0 = blockIdx.x * 128;
    int n0 = blockIdx.y * 128;
    const float* S = g_sim + (size_t)b * NN * NM;
    int w = threadIdx.x >> 5;
    int lane = threadIdx.x & 31;
    int c = m0 + lane * 4;

    float ci[4], cpmax[4] = {0.f, 0.f, 0.f, 0.f};
#pragma unroll
    for (int q = 0; q < 4; q++) ci[q] = 1.0f / g_colsum[b * NM + c + q];

#pragma unroll 2
    for (int r = 0; r < 16; r++) {
        int row = n0 + w * 16 + r;
        float ri = 1.0f / g_rowsum[b * NN + row];
        float4 v = __ldcs((const float4*)(S + (size_t)row * NM + c));
        float vals[4] = {v.x, v.y, v.z, v.w};
        float p[4];
#pragma unroll
        for (int q = 0; q < 4; q++) {
            p[q] = vals[q] * vals[q] * ri * ci[q];
            cpmax[q] = fmaxf(cpmax[q], p[q]);
        }
        float best = p[0];
        int bm = c;
#pragma unroll
        for (int q = 1; q < 4; q++) {
            if (p[q] > best) { best = p[q]; bm = c + q; }
        }
#pragma unroll
        for (int o = 16; o; o >>= 1) {
            float ob = __shfl_xor_sync(0xffffffffu, best, o);
            int obm = __shfl_xor_sync(0xffffffffu, bm, o);
            if (ob > best || (ob == best && obm < bm)) { best = ob; bm = obm; }
        }
        if (lane == 0) {
            unsigned long long pk =
                ((unsigned long long)__float_as_uint(best) << 32) |
                (unsigned)(0x7FFFFFFF - bm);
            atomicMax(&g_rowpack[b * NN + row], pk);
        }
    }

    __shared__ unsigned scp[128];
    if (threadIdx.x < 128) scp[threadIdx.x] = 0u;
    __syncthreads();
#pragma unroll
    for (int q = 0; q < 4; q++) atomicMax(&scp[lane * 4 + q], __float_as_uint(cpmax[q]));
    __syncthreads();
    if (threadIdx.x < 128) atomicMax(&g_colmaxP[b * NM + m0 + threadIdx.x], scp[threadIdx.x]);
}

// ---------------- finalize ----------------
__global__ __launch_bounds__(64) void finalize_kernel(const float* __restrict__ kA,
                                                      const float* __restrict__ descA,
                                                      const float* __restrict__ kB,
                                                      const float* __restrict__ descB,
                                                      const float* __restrict__ W,
                                                      const float* __restrict__ bl,
                                                      float* __restrict__ out) {
    int gid = blockIdx.x;  // b*NN + n
    int b = gid >> 12;
    int t = threadIdx.x;   // 64 threads

    unsigned long long pk = g_rowpack[gid];
    int j = 0x7FFFFFFF - (int)(unsigned)(pk & 0xFFFFFFFFull);
    float Pij = __uint_as_float((unsigned)(pk >> 32));
    float cmj = __uint_as_float(g_colmaxP[b * NM + j]);
    bool valid = (Pij >= cmj) && (Pij > THRESH);

    __shared__ float sa[256], sb_[256];
    const float* arow = descA + (size_t)gid * ND;
    const float* brow = descB + ((size_t)b * NM + j) * ND;
    *(float4*)(sa + t * 4) = *(const float4*)(arow + t * 4);
    *(float4*)(sb_ + t * 4) = *(const float4*)(brow + t * 4);
    __syncthreads();

    float xA = 0.f, xB = 0.f;
#pragma unroll 4
    for (int d = 0; d < ND0; d++) {
        float wd = W[d * NK + t];
        xA = fmaf(sa[d], wd, xA);
        xB = fmaf(sb_[d], wd, xB);
    }
    xA += bl[t];
    xB += bl[t];
    float spA = fmaxf(xA, 0.f) + log1pf(expf(-fabsf(xA)));
    float spB = fmaxf(xB, 0.f) + log1pf(expf(-fabsf(xB)));
    float wk = sqrtf(spA * spB);

    float x0 = sa[ND0 + 2 * t], x1 = sa[ND0 + 2 * t + 1];
    float y0 = sb_[ND0 + 2 * t], y1 = sb_[ND0 + 2 * t + 1];

    float vals[7];
    vals[0] = wk * x0 * x0;
    vals[1] = wk * x0 * x1;
    vals[2] = wk * x1 * x1;
    vals[3] = wk * y0 * x0;
    vals[4] = wk * y0 * x1;
    vals[5] = wk * y1 * x0;
    vals[6] = wk * y1 * x1;

    __shared__ float red[2][7];
#pragma unroll
    for (int i = 0; i < 7; i++) {
        float v = vals[i];
#pragma unroll
        for (int o = 16; o; o >>= 1) v += __shfl_xor_sync(0xffffffffu, v, o);
        if ((t & 31) == 0) red[t >> 5][i] = v;
    }
    __syncthreads();

    if (t == 0) {
        float g00 = red[0][0] + red[1][0] + EPS_G;
        float g01 = red[0][1] + red[1][1];
        float g11 = red[0][2] + red[1][2] + EPS_G;
        float c00 = red[0][3] + red[1][3];
        float c01 = red[0][4] + red[1][4];
        float c10 = red[0][5] + red[1][5];
        float c11 = red[0][6] + red[1][6];

        float dg = g00 * g11 - g01 * g01;
        float e00 = (c00 * g11 - c01 * g01) / dg;
        float e01 = (c01 * g00 - c00 * g01) / dg;
        float e10 = (c10 * g11 - c11 * g01) / dg;
        float e11 = (c11 * g00 - c10 * g01) / dg;

        float M00 = e00 * e00 + e10 * e10;
        float M01 = e00 * e01 + e10 * e11;
        float M11 = e01 * e01 + e11 * e11;
        float tr = M00 + M11;
        float dd = M00 * M11 - M01 * M01;
        float disc = sqrtf(fmaxf(0.25f * tr * tr - dd, 0.f));
        float shi = sqrtf(0.5f * tr + disc);
        float slo = sqrtf(fmaxf(0.5f * tr - disc, 0.f));

        bool good = isfinite(shi + slo) && (shi < 3.0f) && (slo > (1.0f / 3.0f));
        float dete = e00 * e11 - e01 * e10;
        good = good && (dete > 0.f);
        bool vfinal = valid && good;

        const int BN = NB * NN;
        out[(size_t)gid * 2 + 0] = kA[(size_t)gid * 2 + 0];
        out[(size_t)gid * 2 + 1] = kA[(size_t)gid * 2 + 1];
        out[(size_t)BN * 2 + (size_t)gid * 2 + 0] = kB[((size_t)b * NM + j) * 2 + 0];
        out[(size_t)BN * 2 + (size_t)gid * 2 + 1] = kB[((size_t)b * NM + j) * 2 + 1];
        out[(size_t)BN * 4 + gid] = (float)j;
        out[(size_t)BN * 5 + gid] = vfinal ? 1.0f : 0.0f;
    }
}

// ---------------- launch ----------------
extern "C" void kernel_launch(void* const* d_in, const int* in_sizes, int n_in,
                              void* d_out, int out_size) {
    const float* kA = (const float*)d_in[0];
    const float* dA = (const float*)d_in[1];
    const float* kB = (const float*)d_in[2];
    const float* dB = (const float*)d_in[3];
    const float* W = (const float*)d_in[4];
    const float* bl = (const float*)d_in[5];
    float* out = (float*)d_out;

    normalize_split_kernel<<<2 * NB * NN, 256>>>(dA, dB);

    dim3 g(NM / 128, NN / 128, NB);
    gemm16_kernel<<<g, 256>>>();
    reduce_sums_kernel<<<(2 * NB * NN * 32 + 255) / 256, 256>>>();
    pmat_kernel<<<g, 256>>>();
    finalize_kernel<<<NB * NN, 64>>>(kA, dA, kB, dB, W, bl, out);
}

// round 5
// speedup vs baseline: 1.8182x; 1.1062x over previous
#include <cuda_runtime.h>
#include <cuda_fp16.h>
#include <cstdint>
#include <math.h>

#define NB 4
#define NN 4096
#define NM 4096
#define ND 256
#define ND0 128
#define NK 64
#define KP2 512             // stored per row: A=[lo*1024 | hi], B=[hi | lo*1024]
#define ITERS 24            // 16 fp16-acc chunks (cross terms) + 8 fp32-acc chunks (hi*hi)
#define THRESH 0.01f
#define EPS_G 1e-6f
#define LO_SCALE 1024.0f
#define LO_INV (1.0f / 1024.0f)

// ---------------- scratch ----------------
static __device__ __align__(16) __half g_A16[(size_t)NB * NN * KP2];  // 16.8 MB
static __device__ __align__(16) __half g_B16[(size_t)NB * NM * KP2];  // 16.8 MB
static __device__ float g_sim[(size_t)NB * NN * NM];                  // 268 MB (holds e = exp(sim))
static __device__ float g_rowinv[NB * NN];
static __device__ float g_colinv[NB * NM];
static __device__ float g_rowsum_part[NB * NN * 32];
static __device__ float g_colsum_part[NB * NM * 32];
static __device__ int g_rowj[NB * NN];
static __device__ float g_rowP[NB * NN];
static __device__ unsigned g_colmaxP[NB * NM];

__device__ __forceinline__ uint32_t smem_to_u32(const void* p) {
    uint32_t a;
    asm("{ .reg .u64 t; cvta.to.shared.u64 t, %1; cvt.u32.u64 %0, t; }" : "=r"(a) : "l"(p));
    return a;
}

// CUTLASS-style crosswise swizzle for 64B rows: 16B group XOR (row & 3)
__device__ __forceinline__ uint32_t swz(uint32_t r, uint32_t bytecol) {
    return r * 64 + ((((bytecol >> 4) & 3) ^ (r & 3)) << 4) + (bytecol & 15);
}

__device__ __forceinline__ void cpasync16(uint32_t dst, const void* src) {
    asm volatile("cp.async.cg.shared.global [%0], [%1], 16;" :: "r"(dst), "l"(src));
}

__device__ __forceinline__ void ldsm4(uint32_t& d0, uint32_t& d1, uint32_t& d2, uint32_t& d3,
                                      uint32_t addr) {
    asm volatile("ldmatrix.sync.aligned.m8n8.x4.shared.b16 {%0,%1,%2,%3}, [%4];"
                 : "=r"(d0), "=r"(d1), "=r"(d2), "=r"(d3) : "r"(addr));
}

__device__ __forceinline__ void mma16816(float* c, const uint32_t* a, const uint32_t* b) {
    asm volatile(
        "mma.sync.aligned.m16n8k16.row.col.f32.f16.f16.f32 "
        "{%0,%1,%2,%3}, {%4,%5,%6,%7}, {%8,%9}, {%0,%1,%2,%3};"
        : "+f"(c[0]), "+f"(c[1]), "+f"(c[2]), "+f"(c[3])
        : "r"(a[0]), "r"(a[1]), "r"(a[2]), "r"(a[3]), "r"(b[0]), "r"(b[1]));
}

__device__ __forceinline__ void mma16816h(uint32_t* c, const uint32_t* a, const uint32_t* b) {
    asm volatile(
        "mma.sync.aligned.m16n8k16.row.col.f16.f16.f16.f16 "
        "{%0,%1}, {%2,%3,%4,%5}, {%6,%7}, {%0,%1};"
        : "+r"(c[0]), "+r"(c[1])
        : "r"(a[0]), "r"(a[1]), "r"(a[2]), "r"(a[3]), "r"(b[0]), "r"(b[1]));
}

// ---------------- normalize + fp16 split (init folded in) ----------------
__global__ void normalize_split_kernel(const float* __restrict__ descA,
                                       const float* __restrict__ descB) {
    int row = blockIdx.x;  // 0 .. 2*NB*NN-1
    bool isA = row < NB * NN;
    if (isA && threadIdx.x == 0) g_colmaxP[row] = 0u;
    const float* src = isA ? descA + (size_t)row * ND
                           : descB + (size_t)(row - NB * NN) * ND;
    __half* dst = isA ? g_A16 + (size_t)row * KP2
                      : g_B16 + (size_t)(row - NB * NN) * KP2;
    int t = threadIdx.x;  // 256
    float v = src[t];
    float s = v * v;
#pragma unroll
    for (int o = 16; o; o >>= 1) s += __shfl_xor_sync(0xffffffffu, s, o);
    __shared__ float ws[8];
    if ((t & 31) == 0) ws[t >> 5] = s;
    __syncthreads();
    float tot = ws[0] + ws[1] + ws[2] + ws[3] + ws[4] + ws[5] + ws[6] + ws[7];
    float nv = v / sqrtf(tot);
    __half hi = __float2half_rn(nv);
    __half lo = __float2half_rn((nv - __half2float(hi)) * LO_SCALE);
    // A row = [lo' | hi], B row = [hi | lo']
    if (isA) { dst[t] = lo; dst[256 + t] = hi; }
    else     { dst[t] = hi; dst[256 + t] = lo; }
}

// ---------------- HMMA GEMM: cross terms in fp16-acc, hi*hi in fp32-acc ----------------
// 128x128 tile per CTA, 8 warps (2 x 4), each warp 64x32 via m16n8k16.
__global__ __launch_bounds__(256, 2) void gemm16_kernel() {
    __shared__ __align__(128) char buf[49152];  // 3 stages x (A 8KB + B 8KB)

    int tid = threadIdx.x, lane = tid & 31, wid = tid >> 5;
    int warp_m = wid & 1;   // 64-row block of A rows
    int warp_n = wid >> 1;  // 32-row block of B rows
    int b = blockIdx.z;
    int m0 = blockIdx.x * 128;  // B rows
    int n0 = blockIdx.y * 128;  // A rows
    const char* Ag = (const char*)(g_A16 + ((size_t)b * NN + n0) * KP2);
    const char* Bg = (const char*)(g_B16 + ((size_t)b * NM + m0) * KP2);

    uint32_t sbase = smem_to_u32(buf);

    int lr = tid >> 1;        // row 0..127 per load
    int ls = (tid & 1) * 2;   // seg 0 or 2 (two 16B segs each)

    // chunk it: 0..15  -> A=[0,1024) step (lo' then hi wraps? no): see offsets below
    //   it 0..7  : lo'A (A bytes it*64)        x hiB (B bytes it*64)
    //   it 8..15 : hiA  (A bytes it*64 = 512+) x lo'B (B bytes it*64 = 512+)
    //   it 16..23: hiA  (A bytes 512+(it-16)*64) x hiB (B bytes (it-16)*64)
    auto prefetch = [&](int it2) {
        int slot2 = it2 % 3;
        int ao = (it2 < 16) ? it2 * 64 : 512 + (it2 - 16) * 64;
        int bo = (it2 < 16) ? it2 * 64 : (it2 - 16) * 64;
        const char* Ar = Ag + (size_t)lr * (KP2 * 2) + ao;
        const char* Br = Bg + (size_t)lr * (KP2 * 2) + bo;
        uint32_t ab = sbase + slot2 * 8192, bb = sbase + 24576 + slot2 * 8192;
#pragma unroll
        for (int s = 0; s < 2; s++) {
            uint32_t d = swz((uint32_t)lr, (uint32_t)(ls + s) * 16);
            cpasync16(ab + d, Ar + (ls + s) * 16);
            cpasync16(bb + d, Br + (ls + s) * 16);
        }
        asm volatile("cp.async.commit_group;" ::: "memory");
    };

    prefetch(0);
    prefetch(1);

    uint32_t acc16[4][4][2];
#pragma unroll
    for (int i = 0; i < 4; i++)
#pragma unroll
        for (int j = 0; j < 4; j++) { acc16[i][j][0] = 0u; acc16[i][j][1] = 0u; }

    // ---- phase 1: cross terms, fp16 accumulation ----
#pragma unroll 1
    for (int it = 0; it < 16; ++it) {
        if (it < ITERS - 2) {
            asm volatile("cp.async.wait_group 1;" ::: "memory");
        } else {
            asm volatile("cp.async.wait_group 0;" ::: "memory");
        }
        __syncthreads();
        if (it + 2 < ITERS) prefetch(it + 2);

        int slot = it % 3;
        uint32_t ab = sbase + slot * 8192, bb = sbase + 24576 + slot * 8192;
#pragma unroll
        for (int ks = 0; ks < 2; ++ks) {
            uint32_t a[4][4];
#pragma unroll
            for (int mf = 0; mf < 4; ++mf) {
                uint32_t r = warp_m * 64 + mf * 16 + (lane & 15);
                uint32_t bc = ks * 32 + (lane >> 4) * 16;
                ldsm4(a[mf][0], a[mf][1], a[mf][2], a[mf][3], ab + swz(r, bc));
            }
            uint32_t bf[4][2];
#pragma unroll
            for (int np = 0; np < 2; ++np) {
                uint32_t r = warp_n * 32 + np * 16 + (lane & 7) + ((lane >> 4) << 3);
                uint32_t bc = ks * 32 + ((lane >> 3) & 1) * 16;
                uint32_t r0, r1, r2, r3;
                ldsm4(r0, r1, r2, r3, bb + swz(r, bc));
                bf[np * 2][0] = r0; bf[np * 2][1] = r1;
                bf[np * 2 + 1][0] = r2; bf[np * 2 + 1][1] = r3;
            }
#pragma unroll
            for (int mf = 0; mf < 4; ++mf)
#pragma unroll
                for (int nf = 0; nf < 4; ++nf) mma16816h(acc16[mf][nf], a[mf], bf[nf]);
        }
    }

    // ---- convert: acc = acc16 / 1024 ----
    float acc[4][4][4];
#pragma unroll
    for (int mf = 0; mf < 4; ++mf)
#pragma unroll
        for (int nf = 0; nf < 4; ++nf) {
            float2 f0 = __half22float2(*(__half2*)&acc16[mf][nf][0]);
            float2 f1 = __half22float2(*(__half2*)&acc16[mf][nf][1]);
            acc[mf][nf][0] = f0.x * LO_INV;
            acc[mf][nf][1] = f0.y * LO_INV;
            acc[mf][nf][2] = f1.x * LO_INV;
            acc[mf][nf][3] = f1.y * LO_INV;
        }

    // ---- phase 2: hi*hi, fp32 accumulation ----
#pragma unroll 1
    for (int it = 16; it < ITERS; ++it) {
        if (it < ITERS - 2) {
            asm volatile("cp.async.wait_group 1;" ::: "memory");
        } else {
            asm volatile("cp.async.wait_group 0;" ::: "memory");
        }
        __syncthreads();
        if (it + 2 < ITERS) prefetch(it + 2);

        int slot = it % 3;
        uint32_t ab = sbase + slot * 8192, bb = sbase + 24576 + slot * 8192;
#pragma unroll
        for (int ks = 0; ks < 2; ++ks) {
            uint32_t a[4][4];
#pragma unroll
            for (int mf = 0; mf < 4; ++mf) {
                uint32_t r = warp_m * 64 + mf * 16 + (lane & 15);
                uint32_t bc = ks * 32 + (lane >> 4) * 16;
                ldsm4(a[mf][0], a[mf][1], a[mf][2], a[mf][3], ab + swz(r, bc));
            }
            uint32_t bf[4][2];
#pragma unroll
            for (int np = 0; np < 2; ++np) {
                uint32_t r = warp_n * 32 + np * 16 + (lane & 7) + ((lane >> 4) << 3);
                uint32_t bc = ks * 32 + ((lane >> 3) & 1) * 16;
                uint32_t r0, r1, r2, r3;
                ldsm4(r0, r1, r2, r3, bb + swz(r, bc));
                bf[np * 2][0] = r0; bf[np * 2][1] = r1;
                bf[np * 2 + 1][0] = r2; bf[np * 2 + 1][1] = r3;
            }
#pragma unroll
            for (int mf = 0; mf < 4; ++mf)
#pragma unroll
                for (int nf = 0; nf < 4; ++nf) mma16816(acc[mf][nf], a[mf], bf[nf]);
        }
    }
    __syncthreads();  // compute done; reuse buf as reduction scratch

    float (*rowred)[4] = (float(*)[4])buf;            // 128*4 floats
    float (*colred)[2] = (float(*)[2])(buf + 2048);   // 128*2 floats

    // ---------- epilogue: e = exp(20*acc), streaming store, partial row/col sums ----------
    int qt = lane >> 2;  // 0..7 row-in-8
    int qc = lane & 3;   // col pair
    float rsl[4][2];
    float csl[4][2];
#pragma unroll
    for (int i = 0; i < 4; i++) { rsl[i][0] = rsl[i][1] = 0.f; csl[i][0] = csl[i][1] = 0.f; }

    float* S = g_sim + (size_t)b * NN * NM;
#pragma unroll
    for (int mf = 0; mf < 4; ++mf) {
#pragma unroll
        for (int h = 0; h < 2; ++h) {
            int gr = n0 + warp_m * 64 + mf * 16 + qt + 8 * h;
            float* Sr = S + (size_t)gr * NM + m0 + warp_n * 32;
#pragma unroll
            for (int nf = 0; nf < 4; ++nf) {
                float e0 = expf(20.0f * acc[mf][nf][h * 2 + 0]);
                float e1 = expf(20.0f * acc[mf][nf][h * 2 + 1]);
                __stcs((float2*)(Sr + nf * 8 + qc * 2), make_float2(e0, e1));
                rsl[mf][h] += e0 + e1;
                csl[nf][0] += e0;
                csl[nf][1] += e1;
            }
        }
    }

#pragma unroll
    for (int mf = 0; mf < 4; ++mf)
#pragma unroll
        for (int h = 0; h < 2; ++h) {
            float v = rsl[mf][h];
            v += __shfl_xor_sync(0xffffffffu, v, 1);
            v += __shfl_xor_sync(0xffffffffu, v, 2);
            if (qc == 0) rowred[warp_m * 64 + mf * 16 + qt + 8 * h][warp_n] = v;
        }
#pragma unroll
    for (int nf = 0; nf < 4; ++nf)
#pragma unroll
        for (int c = 0; c < 2; ++c) {
            float v = csl[nf][c];
            v += __shfl_xor_sync(0xffffffffu, v, 4);
            v += __shfl_xor_sync(0xffffffffu, v, 8);
            v += __shfl_xor_sync(0xffffffffu, v, 16);
            if (qt == 0) colred[warp_n * 32 + nf * 8 + qc * 2 + c][warp_m] = v;
        }
    __syncthreads();

    if (tid < 128) {
        float rv = rowred[tid][0] + rowred[tid][1] + rowred[tid][2] + rowred[tid][3];
        g_rowsum_part[((size_t)b * NN + n0 + tid) * 32 + blockIdx.x] = rv;
        float cv = colred[tid][0] + colred[tid][1];
        g_colsum_part[((size_t)b * NM + m0 + tid) * 32 + blockIdx.y] = cv;
    }
}

// ---------------- final sum reduction -> reciprocals ----------------
__global__ void reduce_sums_kernel() {
    int warp = (blockIdx.x * blockDim.x + threadIdx.x) >> 5;  // 0..32767
    int lane = threadIdx.x & 31;
    if (warp < NB * NN) {
        float v = g_rowsum_part[warp * 32 + lane];
#pragma unroll
        for (int o = 16; o; o >>= 1) v += __shfl_xor_sync(0xffffffffu, v, o);
        if (lane == 0) g_rowinv[warp] = 1.0f / v;
    } else {
        int k = warp - NB * NN;
        float v = g_colsum_part[k * 32 + lane];
#pragma unroll
        for (int o = 16; o; o >>= 1) v += __shfl_xor_sync(0xffffffffu, v, o);
        if (lane == 0) g_colinv[k] = 1.0f / v;
    }
}

// ---------------- P pass: warp-per-4-rows argmax, shared colmax ----------------
// p = (e*e)*ci*ri ; row argmax uses q=(e*e)*ci (ri>0 uniform); Pij & colmax use q*ri
// (identical expressions -> bit-exact consistency for the mutual-NN compare)
__global__ __launch_bounds__(256) void pmat_kernel() {
    __shared__ unsigned scm[NM];  // 16 KB column max of p (p>=0 -> raw bits monotone)
    int b = blockIdx.y;
    int tid = threadIdx.x, lane = tid & 31, w = tid >> 5;
    int row0 = blockIdx.x * 32 + w * 4;
    const float* S = g_sim + (size_t)b * NN * NM + (size_t)row0 * NM;
    const float* CI = g_colinv + b * NM;

    for (int i = tid; i < NM; i += 256) scm[i] = 0u;

    float ri[4];
#pragma unroll
    for (int r = 0; r < 4; ++r) ri[r] = __ldg(&g_rowinv[b * NN + row0 + r]);

    __syncthreads();

    float best[4] = {-1.f, -1.f, -1.f, -1.f};
    int bm[4] = {0, 0, 0, 0};

#pragma unroll 1
    for (int k = 0; k < 32; ++k) {
        int c = k * 128 + lane * 4;
        float4 civ = __ldg((const float4*)(CI + c));
        float cm[4] = {0.f, 0.f, 0.f, 0.f};
#pragma unroll
        for (int r = 0; r < 4; ++r) {
            float4 e = __ldcs((const float4*)(S + (size_t)r * NM + c));
            float q0 = (e.x * e.x) * civ.x;
            float q1 = (e.y * e.y) * civ.y;
            float q2 = (e.z * e.z) * civ.z;
            float q3 = (e.w * e.w) * civ.w;
            if (q0 > best[r]) { best[r] = q0; bm[r] = c; }
            if (q1 > best[r]) { best[r] = q1; bm[r] = c + 1; }
            if (q2 > best[r]) { best[r] = q2; bm[r] = c + 2; }
            if (q3 > best[r]) { best[r] = q3; bm[r] = c + 3; }
            cm[0] = fmaxf(cm[0], q0 * ri[r]);
            cm[1] = fmaxf(cm[1], q1 * ri[r]);
            cm[2] = fmaxf(cm[2], q2 * ri[r]);
            cm[3] = fmaxf(cm[3], q3 * ri[r]);
        }
        atomicMax(&scm[c + 0], __float_as_uint(cm[0]));
        atomicMax(&scm[c + 1], __float_as_uint(cm[1]));
        atomicMax(&scm[c + 2], __float_as_uint(cm[2]));
        atomicMax(&scm[c + 3], __float_as_uint(cm[3]));
    }

    // per-row warp reduction (first-occurrence tie-break: smaller m wins on tie)
#pragma unroll
    for (int r = 0; r < 4; ++r) {
        float bq = best[r];
        int bj = bm[r];
#pragma unroll
        for (int o = 16; o; o >>= 1) {
            float ob = __shfl_xor_sync(0xffffffffu, bq, o);
            int obj = __shfl_xor_sync(0xffffffffu, bj, o);
            if (ob > bq || (ob == bq && obj < bj)) { bq = ob; bj = obj; }
        }
        if (lane == 0) {
            g_rowj[b * NN + row0 + r] = bj;
            g_rowP[b * NN + row0 + r] = bq * ri[r];
        }
    }

    __syncthreads();
    for (int i = tid; i < NM; i += 256)
        atomicMax(&g_colmaxP[b * NM + i], scm[i]);
}

// ---------------- finalize ----------------
__global__ __launch_bounds__(64) void finalize_kernel(const float* __restrict__ kA,
                                                      const float* __restrict__ descA,
                                                      const float* __restrict__ kB,
                                                      const float* __restrict__ descB,
                                                      const float* __restrict__ W,
                                                      const float* __restrict__ bl,
                                                      float* __restrict__ out) {
    int gid = blockIdx.x;  // b*NN + n
    int b = gid >> 12;
    int t = threadIdx.x;   // 64 threads

    int j = g_rowj[gid];
    float Pij = g_rowP[gid];
    float cmj = __uint_as_float(g_colmaxP[b * NM + j]);
    bool valid = (Pij >= cmj) && (Pij > THRESH);

    __shared__ float sa[256], sb_[256];
    const float* arow = descA + (size_t)gid * ND;
    const float* brow = descB + ((size_t)b * NM + j) * ND;
    *(float4*)(sa + t * 4) = *(const float4*)(arow + t * 4);
    *(float4*)(sb_ + t * 4) = *(const float4*)(brow + t * 4);
    __syncthreads();

    float xA = 0.f, xB = 0.f;
#pragma unroll 4
    for (int d = 0; d < ND0; d++) {
        float wd = W[d * NK + t];
        xA = fmaf(sa[d], wd, xA);
        xB = fmaf(sb_[d], wd, xB);
    }
    xA += bl[t];
    xB += bl[t];
    float spA = fmaxf(xA, 0.f) + log1pf(expf(-fabsf(xA)));
    float spB = fmaxf(xB, 0.f) + log1pf(expf(-fabsf(xB)));
    float wk = sqrtf(spA * spB);

    float x0 = sa[ND0 + 2 * t], x1 = sa[ND0 + 2 * t + 1];
    float y0 = sb_[ND0 + 2 * t], y1 = sb_[ND0 + 2 * t + 1];

    float vals[7];
    vals[0] = wk * x0 * x0;
    vals[1] = wk * x0 * x1;
    vals[2] = wk * x1 * x1;
    vals[3] = wk * y0 * x0;
    vals[4] = wk * y0 * x1;
    vals[5] = wk * y1 * x0;
    vals[6] = wk * y1 * x1;

    __shared__ float red[2][7];
#pragma unroll
    for (int i = 0; i < 7; i++) {
        float v = vals[i];
#pragma unroll
        for (int o = 16; o; o >>= 1) v += __shfl_xor_sync(0xffffffffu, v, o);
        if ((t & 31) == 0) red[t >> 5][i] = v;
    }
    __syncthreads();

    if (t == 0) {
        float g00 = red[0][0] + red[1][0] + EPS_G;
        float g01 = red[0][1] + red[1][1];
        float g11 = red[0][2] + red[1][2] + EPS_G;
        float c00 = red[0][3] + red[1][3];
        float c01 = red[0][4] + red[1][4];
        float c10 = red[0][5] + red[1][5];
        float c11 = red[0][6] + red[1][6];

        float dg = g00 * g11 - g01 * g01;
        float e00 = (c00 * g11 - c01 * g01) / dg;
        float e01 = (c01 * g00 - c00 * g01) / dg;
        float e10 = (c10 * g11 - c11 * g01) / dg;
        float e11 = (c11 * g00 - c10 * g01) / dg;

        float M00 = e00 * e00 + e10 * e10;
        float M01 = e00 * e01 + e10 * e11;
        float M11 = e01 * e01 + e11 * e11;
        float tr = M00 + M11;
        float dd = M00 * M11 - M01 * M01;
        float disc = sqrtf(fmaxf(0.25f * tr * tr - dd, 0.f));
        float shi = sqrtf(0.5f * tr + disc);
        float slo = sqrtf(fmaxf(0.5f * tr - disc, 0.f));

        bool good = isfinite(shi + slo) && (shi < 3.0f) && (slo > (1.0f / 3.0f));
        float dete = e00 * e11 - e01 * e10;
        good = good && (dete > 0.f);
        bool vfinal = valid && good;

        const int BN = NB * NN;
        out[(size_t)gid * 2 + 0] = kA[(size_t)gid * 2 + 0];
        out[(size_t)gid * 2 + 1] = kA[(size_t)gid * 2 + 1];
        out[(size_t)BN * 2 + (size_t)gid * 2 + 0] = kB[((size_t)b * NM + j) * 2 + 0];
        out[(size_t)BN * 2 + (size_t)gid * 2 + 1] = kB[((size_t)b * NM + j) * 2 + 1];
        out[(size_t)BN * 4 + gid] = (float)j;
        out[(size_t)BN * 5 + gid] = vfinal ? 1.0f : 0.0f;
    }
}

// ---------------- launch ----------------
extern "C" void kernel_launch(void* const* d_in, const int* in_sizes, int n_in,
                              void* d_out, int out_size) {
    const float* kA = (const float*)d_in[0];
    const float* dA = (const float*)d_in[1];
    const float* kB = (const float*)d_in[2];
    const float* dB = (const float*)d_in[3];
    const float* W = (const float*)d_in[4];
    const float* bl = (const float*)d_in[5];
    float* out = (float*)d_out;

    normalize_split_kernel<<<2 * NB * NN, 256>>>(dA, dB);

    dim3 g(NM / 128, NN / 128, NB);
    gemm16_kernel<<<g, 256>>>();
    reduce_sums_kernel<<<(2 * NB * NN * 32 + 255) / 256, 256>>>();
    pmat_kernel<<<dim3(NN / 32, NB), 256>>>();
    finalize_kernel<<<NB * NN, 64>>>(kA, dA, kB, dB, W, bl, out);
}